// round 8
// baseline (speedup 1.0000x reference)
#include <cuda_runtime.h>
#include <cstdint>
#include <cstddef>

#define D        1024
#define D4       256
#define NS       25
#define NWAY     5
#define SP       1028      // S pitch in floats (1024 + 4)
#define AUGC     32        // augmented matrix row stride
#define MAXB     1024
#define ROWS_PER_CTA 16    // logits: 8 warps x 2 rows

// global scratch: W^T per batch, class-major
__device__ float g_Wt[MAXB * NWAY * D];

// tile map: 15 upper-triangle pairs of 5 row-blocks
__constant__ unsigned char c_bi[15] = {0,0,0,0,0,1,1,1,1,2,2,2,3,3,4};
__constant__ unsigned char c_bj[15] = {0,1,2,3,4,1,2,3,4,2,3,4,3,4,4};

__device__ __forceinline__ void fma2(unsigned long long& d,
                                     unsigned long long a,
                                     unsigned long long b) {
    asm("fma.rn.f32x2 %0, %1, %2, %0;" : "+l"(d) : "l"(a), "l"(b));
}

// ---------------------------------------------------------------------------
// Kernel 1 (prep): per batch — load S once, K = S S^T (full k in registers),
//                  warp-0 Gauss-Jordan, W^T = S^T A  -> g_Wt.     grid(B)
// ---------------------------------------------------------------------------
struct SmP {
    float S[NS * SP];        // 102800 B
    float M[NS * AUGC];      //   3200 B
};                           // 106000 B total -> 2 CTAs/SM

__global__ void __launch_bounds__(256)
prep_kernel(const float* __restrict__ support,
            const void* __restrict__ labels_raw,
            float* __restrict__ wt_out)
{
    extern __shared__ __align__(16) char smem_raw[];
    SmP* sm = reinterpret_cast<SmP*>(smem_raw);

    const int b    = blockIdx.x;
    const int tid  = threadIdx.x;
    const int lane = tid & 31;
    const int warp = tid >> 5;

    // ---- Phase 0: zero M's Y/pad columns; load full S tile ----------------
    for (int s = tid; s < NS * (AUGC - NS); s += 256) {
        int i = s / (AUGC - NS), j = s - i * (AUGC - NS);
        sm->M[i * AUGC + NS + j] = 0.0f;
    }
    const float4* Sg4 = reinterpret_cast<const float4*>(support + (size_t)b * NS * D);
    for (int idx = tid; idx < NS * D4; idx += 256) {
        int row  = idx >> 8;            // idx / 256
        int col4 = idx & 255;
        float4 v = Sg4[idx];
        float* dst = &sm->S[row * SP + col4 * 4];
        dst[0] = v.x; dst[1] = v.y; dst[2] = v.z; dst[3] = v.w;
    }
    __syncthreads();

    // ---- Phase 1: K = S S^T, 15 upper-triangle 5x5 tiles, full k=1024 -----
    for (int t = warp; t < 15; t += 8) {
        const int bi = c_bi[t] * 5;
        const int bj = c_bj[t] * 5;

        unsigned long long acc[5][5];    // packed f32x2 partials
        #pragma unroll
        for (int r = 0; r < 5; r++)
            #pragma unroll
            for (int s = 0; s < 5; s++) acc[r][s] = 0ull;

        #pragma unroll
        for (int it = 0; it < 8; it++) {
            const int k = (lane + 32 * it) * 4;
            ulonglong2 a[5];
            #pragma unroll
            for (int r = 0; r < 5; r++)
                a[r] = *reinterpret_cast<const ulonglong2*>(&sm->S[(bi + r) * SP + k]);
            #pragma unroll
            for (int s = 0; s < 5; s++) {
                ulonglong2 bv = *reinterpret_cast<const ulonglong2*>(&sm->S[(bj + s) * SP + k]);
                #pragma unroll
                for (int r = 0; r < 5; r++) {
                    fma2(acc[r][s], a[r].x, bv.x);
                    fma2(acc[r][s], a[r].y, bv.y);
                }
            }
        }
        #pragma unroll
        for (int r = 0; r < 5; r++)
            #pragma unroll
            for (int s = 0; s < 5; s++) {
                float v = __uint_as_float((unsigned)acc[r][s]) +
                          __uint_as_float((unsigned)(acc[r][s] >> 32));
                #pragma unroll
                for (int o = 16; o > 0; o >>= 1)
                    v += __shfl_xor_sync(0xffffffffu, v, o);
                if (lane == 0) {
                    const int i = bi + r, j = bj + s;
                    // duplicate writes (diagonal tiles) are bit-identical
                    sm->M[i * AUGC + j] = v;
                    sm->M[j * AUGC + i] = v;
                }
            }
    }
    __syncthreads();

    // ---- Phase 2: warp 0: +lambda*I, Y one-hot, Gauss-Jordan ---------------
    if (warp == 0) {
        if (lane < NS)
            sm->M[lane * AUGC + lane] += 1.0f;      // + lambda * I

        // label dtype detection (int64 vs int32) via first 25 entries
        const int* li = reinterpret_cast<const int*>(labels_raw);
        int hi = (lane < NS) ? li[2 * lane + 1] : 0;
        unsigned nz = __ballot_sync(0xffffffffu, hi != 0);
        bool is64 = (nz == 0);

        if (lane < NS) {
            long long lbl;
            if (is64)
                lbl = reinterpret_cast<const long long*>(labels_raw)[(size_t)b * NS + lane];
            else
                lbl = (long long)li[(size_t)b * NS + lane];
            sm->M[lane * AUGC + NS + (int)lbl] = 1.0f;
        }
        __syncwarp();

        // Gauss-Jordan, SPD, no pivoting; columns j < p already identity
        for (int p = 0; p < NS; p++) {
            const float inv = 1.0f / sm->M[p * AUGC + p];
            const float fr  = (lane < NS) ? sm->M[lane * AUGC + p] : 0.f;
            __syncwarp();
            const int ncols = 30 - p;
            if (lane < ncols) sm->M[p * AUGC + p + lane] *= inv;
            __syncwarp();
            const int total = NS * ncols;
            for (int base = 0; base < total; base += 32) {
                const int s = base + lane;
                int i = 0, j = 0;
                bool act = (s < total);
                if (act) { i = s / ncols; j = p + (s - i * ncols); }
                act = act && (i != p);
                float f  = __shfl_sync(0xffffffffu, fr, act ? i : 0);
                float pv = sm->M[p * AUGC + (act ? j : p)];
                if (act) sm->M[i * AUGC + j] -= f * pv;
            }
            __syncwarp();
        }
    }
    __syncthreads();
    // A[i][c] at M[i][25 + c]

    // ---- Phase 3: W^T[c][k] = sum_i S[i][k] A[i][c]  (S from smem) --------
    {
        float4 acc[NWAY];
        #pragma unroll
        for (int c = 0; c < NWAY; c++) acc[c] = make_float4(0.f, 0.f, 0.f, 0.f);
        #pragma unroll
        for (int i = 0; i < NS; i++) {
            float4 s = *reinterpret_cast<const float4*>(&sm->S[i * SP + tid * 4]);
            #pragma unroll
            for (int c = 0; c < NWAY; c++) {
                float a = sm->M[i * AUGC + NS + c];
                acc[c].x += s.x * a; acc[c].y += s.y * a;
                acc[c].z += s.z * a; acc[c].w += s.w * a;
            }
        }
        float4* Wt4 = reinterpret_cast<float4*>(wt_out + (size_t)b * NWAY * D);
        #pragma unroll
        for (int c = 0; c < NWAY; c++)
            Wt4[c * D4 + tid] = acc[c];
    }
}

// ---------------------------------------------------------------------------
// Kernel 2: logits = scale * Q @ W   (R4 measured-good config, unchanged)
// ---------------------------------------------------------------------------
struct SmB { float Wt[NWAY * D]; };   // 20480 B

__global__ void __launch_bounds__(256, 5)
logits_kernel(const float* __restrict__ query,
              const float* __restrict__ wt_in,
              const float* __restrict__ scale,
              float* __restrict__ out,
              int NQ)
{
    extern __shared__ __align__(16) char smem_raw[];
    SmB* sm = reinterpret_cast<SmB*>(smem_raw);

    const int b    = blockIdx.y;
    const int sub  = blockIdx.x;
    const int tid  = threadIdx.x;
    const int lane = tid & 31;
    const int warp = tid >> 5;

    // load W^T tile (1280 float4 / 256 threads = 5 each)
    {
        const float4* src = reinterpret_cast<const float4*>(wt_in + (size_t)b * NWAY * D);
        float4* dst = reinterpret_cast<float4*>(sm->Wt);
        #pragma unroll
        for (int i = 0; i < 5; i++)
            dst[tid + i * 256] = src[tid + i * 256];
    }
    __syncthreads();

    const int row0 = sub * ROWS_PER_CTA;
    const int rows = min(ROWS_PER_CTA, NQ - row0);
    if (rows <= 0) return;

    const int r0 = warp * 2;
    const bool v0 = r0 < rows;
    const bool v1 = r0 + 1 < rows;
    if (!v0) return;

    const float* Qg = query + ((size_t)b * NQ + row0) * D;
    const float4* q0 = reinterpret_cast<const float4*>(Qg + (size_t)r0 * D);
    const float4* q1 = reinterpret_cast<const float4*>(Qg + (size_t)(r0 + 1) * D);

    float acc0[NWAY] = {0.f, 0.f, 0.f, 0.f, 0.f};
    float acc1[NWAY] = {0.f, 0.f, 0.f, 0.f, 0.f};

    #pragma unroll
    for (int it = 0; it < 8; it++) {
        const int k4 = lane + 32 * it;
        float4 qa = q0[k4];
        float4 qb = v1 ? q1[k4] : make_float4(0.f, 0.f, 0.f, 0.f);
        #pragma unroll
        for (int c = 0; c < NWAY; c++) {
            float4 w = *reinterpret_cast<const float4*>(&sm->Wt[c * D + k4 * 4]);
            acc0[c] += qa.x * w.x + qa.y * w.y + qa.z * w.z + qa.w * w.w;
            acc1[c] += qb.x * w.x + qb.y * w.y + qb.z * w.z + qb.w * w.w;
        }
    }

    const float scl = __ldg(scale);
    float* Ob = out + ((size_t)b * NQ + row0 + r0) * NWAY;
    #pragma unroll
    for (int c = 0; c < NWAY; c++) {
        float x = acc0[c], y = acc1[c];
        #pragma unroll
        for (int o = 16; o > 0; o >>= 1) {
            x += __shfl_xor_sync(0xffffffffu, x, o);
            y += __shfl_xor_sync(0xffffffffu, y, o);
        }
        if (lane == 0) {
            Ob[c] = scl * x;
            if (v1) Ob[NWAY + c] = scl * y;
        }
    }
}

extern "C" void kernel_launch(void* const* d_in, const int* in_sizes, int n_in,
                              void* d_out, int out_size)
{
    const float* query   = (const float*)d_in[0];
    const float* support = (const float*)d_in[1];
    const void*  labels  = d_in[2];
    const float* scale   = (const float*)d_in[3];

    const int B  = in_sizes[1] / (NS * D);
    const int NQ = in_sizes[0] / (B * D);

    float* wt;
    cudaGetSymbolAddress((void**)&wt, g_Wt);

    cudaFuncSetAttribute(prep_kernel,
                         cudaFuncAttributeMaxDynamicSharedMemorySize, (int)sizeof(SmP));
    cudaFuncSetAttribute(logits_kernel,
                         cudaFuncAttributeMaxDynamicSharedMemorySize, (int)sizeof(SmB));

    prep_kernel<<<B, 256, sizeof(SmP)>>>(support, labels, wt);

    dim3 g3((NQ + ROWS_PER_CTA - 1) / ROWS_PER_CTA, B);
    logits_kernel<<<g3, 256, sizeof(SmB)>>>(query, wt, scale, (float*)d_out, NQ);
}

// round 9
// speedup vs baseline: 1.4467x; 1.4467x over previous
#include <cuda_runtime.h>
#include <cstdint>
#include <cstddef>

#define D        1024
#define D4       256
#define NS       25
#define NWAY     5
#define NCHUNK   4
#define CW       256       // chunk width (floats)
#define CW4      64
#define CP       260       // chunk pitch (floats)
#define SROWS    28        // 25 rows padded to 28 (7 blocks of 4)
#define AUGC     32        // augmented matrix row stride
#define MAXB     1024
#define ROWS_PER_CTA 16    // logits: 8 warps x 2 rows

// global scratch
__device__ float g_Kp[MAXB * NCHUNK * NS * NS];  // partial K per chunk
__device__ float g_Wt[MAXB * NWAY * D];          // W^T class-major

// tile map: 28 upper-triangle pairs of 7 row-blocks (4 rows each)
__constant__ unsigned char t_bi[28] =
    {0,0,0,0,0,0,0, 1,1,1,1,1,1, 2,2,2,2,2, 3,3,3,3, 4,4,4, 5,5, 6};
__constant__ unsigned char t_bj[28] =
    {0,1,2,3,4,5,6, 1,2,3,4,5,6, 2,3,4,5,6, 3,4,5,6, 4,5,6, 5,6, 6};

// ---------------------------------------------------------------------------
// Kernel 1: partial K = S_chunk S_chunk^T  -> g_Kp   grid(NCHUNK, B)
//           4x4 register tiles, 5 CTAs/SM (reg-budgeted)
// ---------------------------------------------------------------------------
struct SmK { float Sc[SROWS * CP]; };             // 29120 B

__global__ void __launch_bounds__(256, 5)
kpart_kernel(const float* __restrict__ support, float* __restrict__ kp)
{
    extern __shared__ __align__(16) char smem_raw[];
    SmK* sm = reinterpret_cast<SmK*>(smem_raw);

    const int ch   = blockIdx.x;
    const int b    = blockIdx.y;
    const int tid  = threadIdx.x;
    const int lane = tid & 31;
    const int warp = tid >> 5;

    const float4* Sg4 = reinterpret_cast<const float4*>(support + (size_t)b * NS * D);

    // load 28 x 256 chunk (rows 25..27 zero)
    for (int idx = tid; idx < SROWS * CW4; idx += 256) {
        int row = idx / CW4;
        int k4  = idx - row * CW4;
        float4 v = make_float4(0.f, 0.f, 0.f, 0.f);
        if (row < NS)
            v = Sg4[row * D4 + ch * CW4 + k4];
        float* dst = &sm->Sc[row * CP + k4 * 4];
        dst[0] = v.x; dst[1] = v.y; dst[2] = v.z; dst[3] = v.w;
    }
    __syncthreads();

    float* outp = kp + ((size_t)b * NCHUNK + ch) * NS * NS;

    // 28 upper-triangle 4x4 block tiles over 8 warps
    for (int t = warp; t < 28; t += 8) {
        const int bi = t_bi[t] * 4;
        const int bj = t_bj[t] * 4;

        float acc[4][4];
        #pragma unroll
        for (int r = 0; r < 4; r++)
            #pragma unroll
            for (int s = 0; s < 4; s++) acc[r][s] = 0.f;

        #pragma unroll
        for (int it = 0; it < 2; it++) {
            const int k = (lane + 32 * it) * 4;
            float4 a[4];
            #pragma unroll
            for (int r = 0; r < 4; r++)
                a[r] = *reinterpret_cast<const float4*>(&sm->Sc[(bi + r) * CP + k]);
            #pragma unroll
            for (int s = 0; s < 4; s++) {
                float4 bv = *reinterpret_cast<const float4*>(&sm->Sc[(bj + s) * CP + k]);
                #pragma unroll
                for (int r = 0; r < 4; r++)
                    acc[r][s] += a[r].x * bv.x + a[r].y * bv.y +
                                 a[r].z * bv.z + a[r].w * bv.w;
            }
        }
        #pragma unroll
        for (int r = 0; r < 4; r++)
            #pragma unroll
            for (int s = 0; s < 4; s++) {
                float v = acc[r][s];
                #pragma unroll
                for (int o = 16; o > 0; o >>= 1)
                    v += __shfl_xor_sync(0xffffffffu, v, o);
                if (lane == 0) {
                    const int i = bi + r, j = bj + s;
                    if (i < NS && j < NS) {
                        // duplicate writes (diagonal tiles) are bit-identical
                        outp[i * NS + j] = v;
                        outp[j * NS + i] = v;
                    }
                }
            }
    }
}

// ---------------------------------------------------------------------------
// Kernel 2: fused: reduce K partials + block-parallel Gauss-Jordan + W = S^T A
//           grid(B), block 256
// ---------------------------------------------------------------------------
__global__ void __launch_bounds__(256, 5)
solve_w_kernel(const float* __restrict__ kp,
               const void* __restrict__ labels_raw,
               const float* __restrict__ support,
               float* __restrict__ wt_out)
{
    __shared__ float M[NS * AUGC];
    __shared__ float f[32];
    const int b    = blockIdx.x;
    const int tid  = threadIdx.x;
    const int lane = tid & 31;
    const int warp = tid >> 5;

    // ---- reduce 4 chunk partials + lambda*I (all threads) ----------------
    const float* p0 = kp + (size_t)b * NCHUNK * NS * NS;
    for (int s = tid; s < NS * NS; s += 256) {
        int i = s / NS, j = s - i * NS;
        float v = p0[s] + p0[s + NS * NS] + p0[s + 2 * NS * NS] + p0[s + 3 * NS * NS];
        if (i == j) v += 1.0f;
        M[i * AUGC + j] = v;
    }
    for (int s = tid; s < NS * (AUGC - NS); s += 256) {
        int i = s / (AUGC - NS), j = s - i * (AUGC - NS);
        M[i * AUGC + NS + j] = 0.0f;
    }
    __syncthreads();

    if (warp == 0) {
        // label dtype detection (int64 vs int32) via first 25 entries
        const int* li = reinterpret_cast<const int*>(labels_raw);
        int hi = (lane < NS) ? li[2 * lane + 1] : 0;
        unsigned nz = __ballot_sync(0xffffffffu, hi != 0);
        bool is64 = (nz == 0);

        if (lane < NS) {
            long long lbl;
            if (is64)
                lbl = reinterpret_cast<const long long*>(labels_raw)[(size_t)b * NS + lane];
            else
                lbl = (long long)li[(size_t)b * NS + lane];
            M[lane * AUGC + NS + (int)lbl] = 1.0f;
        }
    }
    __syncthreads();

    // ---- block-parallel Gauss-Jordan (SPD, no pivoting, column-skip) -----
    for (int p = 0; p < NS; p++) {
        // phase 1: save pivot column (pre-scale) and scale pivot row.
        // disjoint smem regions (col i!=p vs row p), safe in one phase.
        const float inv = 1.0f / M[p * AUGC + p];
        if (tid < NS) {
            if (tid != p) f[tid] = M[tid * AUGC + p];
        } else if (tid >= 32 && tid < 64) {
            const int j = tid - 32;
            if (j >= p && j < 30) M[p * AUGC + j] *= inv;
        }
        __syncthreads();
        // phase 2: update rows i != p, columns j in [p, 30).
        // 25x32 grid, stride mapping (no divides); predicate off j<p, j>=30.
        #pragma unroll
        for (int it = 0; it < 4; it++) {
            const int s = tid + it * 256;
            const int i = s >> 5;
            const int j = s & 31;
            if (i < NS && i != p && j >= p && j < 30)
                M[i * AUGC + j] -= f[i] * M[p * AUGC + j];
        }
        __syncthreads();
    }
    // A[i][c] at M[i][25 + c]

    // ---- W^T[c][k] = sum_i S[i][k] A[i][c]  (S from L2) -------------------
    const float4* Sg4 = reinterpret_cast<const float4*>(support + (size_t)b * NS * D);
    float4 acc[NWAY];
    #pragma unroll
    for (int c = 0; c < NWAY; c++) acc[c] = make_float4(0.f, 0.f, 0.f, 0.f);

    #pragma unroll
    for (int i = 0; i < NS; i++) {
        float4 s = __ldg(&Sg4[i * D4 + tid]);
        #pragma unroll
        for (int c = 0; c < NWAY; c++) {
            float a = M[i * AUGC + NS + c];
            acc[c].x += s.x * a; acc[c].y += s.y * a;
            acc[c].z += s.z * a; acc[c].w += s.w * a;
        }
    }
    float4* Wt4 = reinterpret_cast<float4*>(wt_out + (size_t)b * NWAY * D);
    #pragma unroll
    for (int c = 0; c < NWAY; c++)
        Wt4[c * D4 + tid] = acc[c];
}

// ---------------------------------------------------------------------------
// Kernel 3: logits = scale * Q @ W   (R4 measured-good config, FROZEN)
// ---------------------------------------------------------------------------
struct SmB { float Wt[NWAY * D]; };   // 20480 B

__global__ void __launch_bounds__(256, 5)
logits_kernel(const float* __restrict__ query,
              const float* __restrict__ wt_in,
              const float* __restrict__ scale,
              float* __restrict__ out,
              int NQ)
{
    extern __shared__ __align__(16) char smem_raw[];
    SmB* sm = reinterpret_cast<SmB*>(smem_raw);

    const int b    = blockIdx.y;
    const int sub  = blockIdx.x;
    const int tid  = threadIdx.x;
    const int lane = tid & 31;
    const int warp = tid >> 5;

    // load W^T tile (1280 float4 / 256 threads = 5 each)
    {
        const float4* src = reinterpret_cast<const float4*>(wt_in + (size_t)b * NWAY * D);
        float4* dst = reinterpret_cast<float4*>(sm->Wt);
        #pragma unroll
        for (int i = 0; i < 5; i++)
            dst[tid + i * 256] = src[tid + i * 256];
    }
    __syncthreads();

    const int row0 = sub * ROWS_PER_CTA;
    const int rows = min(ROWS_PER_CTA, NQ - row0);
    if (rows <= 0) return;

    const int r0 = warp * 2;
    const bool v0 = r0 < rows;
    const bool v1 = r0 + 1 < rows;
    if (!v0) return;

    const float* Qg = query + ((size_t)b * NQ + row0) * D;
    const float4* q0 = reinterpret_cast<const float4*>(Qg + (size_t)r0 * D);
    const float4* q1 = reinterpret_cast<const float4*>(Qg + (size_t)(r0 + 1) * D);

    float acc0[NWAY] = {0.f, 0.f, 0.f, 0.f, 0.f};
    float acc1[NWAY] = {0.f, 0.f, 0.f, 0.f, 0.f};

    #pragma unroll
    for (int it = 0; it < 8; it++) {
        const int k4 = lane + 32 * it;
        float4 qa = q0[k4];
        float4 qb = v1 ? q1[k4] : make_float4(0.f, 0.f, 0.f, 0.f);
        #pragma unroll
        for (int c = 0; c < NWAY; c++) {
            float4 w = *reinterpret_cast<const float4*>(&sm->Wt[c * D + k4 * 4]);
            acc0[c] += qa.x * w.x + qa.y * w.y + qa.z * w.z + qa.w * w.w;
            acc1[c] += qb.x * w.x + qb.y * w.y + qb.z * w.z + qb.w * w.w;
        }
    }

    const float scl = __ldg(scale);
    float* Ob = out + ((size_t)b * NQ + row0 + r0) * NWAY;
    #pragma unroll
    for (int c = 0; c < NWAY; c++) {
        float x = acc0[c], y = acc1[c];
        #pragma unroll
        for (int o = 16; o > 0; o >>= 1) {
            x += __shfl_xor_sync(0xffffffffu, x, o);
            y += __shfl_xor_sync(0xffffffffu, y, o);
        }
        if (lane == 0) {
            Ob[c] = scl * x;
            if (v1) Ob[NWAY + c] = scl * y;
        }
    }
}

extern "C" void kernel_launch(void* const* d_in, const int* in_sizes, int n_in,
                              void* d_out, int out_size)
{
    const float* query   = (const float*)d_in[0];
    const float* support = (const float*)d_in[1];
    const void*  labels  = d_in[2];
    const float* scale   = (const float*)d_in[3];

    const int B  = in_sizes[1] / (NS * D);
    const int NQ = in_sizes[0] / (B * D);

    float *kp, *wt;
    cudaGetSymbolAddress((void**)&kp, g_Kp);
    cudaGetSymbolAddress((void**)&wt, g_Wt);

    cudaFuncSetAttribute(kpart_kernel,
                         cudaFuncAttributeMaxDynamicSharedMemorySize, (int)sizeof(SmK));
    cudaFuncSetAttribute(logits_kernel,
                         cudaFuncAttributeMaxDynamicSharedMemorySize, (int)sizeof(SmB));

    dim3 g1(NCHUNK, B);
    kpart_kernel<<<g1, 256, sizeof(SmK)>>>(support, kp);

    solve_w_kernel<<<B, 256>>>(kp, labels, support, wt);

    dim3 g3((NQ + ROWS_PER_CTA - 1) / ROWS_PER_CTA, B);
    logits_kernel<<<g3, 256, sizeof(SmB)>>>(query, wt, scale, (float*)d_out, NQ);
}

// round 10
// speedup vs baseline: 1.7551x; 1.2132x over previous
#include <cuda_runtime.h>
#include <cstdint>
#include <cstddef>

#define D        1024
#define D4       256
#define NS       25
#define NWAY     5
#define NCHUNK   4
#define CW       256       // chunk width (floats)
#define CW4      64
#define CP       260       // chunk pitch (floats)
#define SROWS    28        // 25 rows padded to 28 (7 blocks of 4)
#define AUGC     32        // augmented matrix row stride
#define MAXB     1024
#define ROWS_PER_CTA 16    // logits: 8 warps x 2 rows

// global scratch
__device__ float g_Kp[MAXB * NCHUNK * NS * NS];  // partial K per chunk
__device__ float g_Wt[MAXB * NWAY * D];          // W^T class-major

// tile map: 28 upper-triangle pairs of 7 row-blocks (4 rows each)
__constant__ unsigned char t_bi[28] =
    {0,0,0,0,0,0,0, 1,1,1,1,1,1, 2,2,2,2,2, 3,3,3,3, 4,4,4, 5,5, 6};
__constant__ unsigned char t_bj[28] =
    {0,1,2,3,4,5,6, 1,2,3,4,5,6, 2,3,4,5,6, 3,4,5,6, 4,5,6, 5,6, 6};

// Multi-value butterfly: reduces 16 per-lane partials across the warp with
// 16 shuffles total. On exit, lane pair (2m, 2m+1) holds the full sum of
// acc[m] (m = (lane >> 1) & 15).
__device__ __forceinline__ void reduce16(float* a, int lane) {
    // offset 16: keep 8
    {
        const bool hi = (lane & 16) != 0;
        #pragma unroll
        for (int m = 0; m < 8; m++) {
            float mine  = hi ? a[m + 8] : a[m];
            float other = hi ? a[m]     : a[m + 8];
            a[m] = mine + __shfl_xor_sync(0xffffffffu, other, 16);
        }
    }
    // offset 8: keep 4
    {
        const bool hi = (lane & 8) != 0;
        #pragma unroll
        for (int m = 0; m < 4; m++) {
            float mine  = hi ? a[m + 4] : a[m];
            float other = hi ? a[m]     : a[m + 4];
            a[m] = mine + __shfl_xor_sync(0xffffffffu, other, 8);
        }
    }
    // offset 4: keep 2
    {
        const bool hi = (lane & 4) != 0;
        #pragma unroll
        for (int m = 0; m < 2; m++) {
            float mine  = hi ? a[m + 2] : a[m];
            float other = hi ? a[m]     : a[m + 2];
            a[m] = mine + __shfl_xor_sync(0xffffffffu, other, 4);
        }
    }
    // offset 2: keep 1
    {
        const bool hi = (lane & 2) != 0;
        float mine  = hi ? a[1] : a[0];
        float other = hi ? a[0] : a[1];
        a[0] = mine + __shfl_xor_sync(0xffffffffu, other, 2);
    }
    // offset 1: finish
    a[0] += __shfl_xor_sync(0xffffffffu, a[0], 1);
}

// ---------------------------------------------------------------------------
// Kernel 1: partial K = S_chunk S_chunk^T  -> g_Kp   grid(NCHUNK, B)
// ---------------------------------------------------------------------------
struct SmK { float Sc[SROWS * CP]; };             // 29120 B

__global__ void __launch_bounds__(256, 5)
kpart_kernel(const float* __restrict__ support, float* __restrict__ kp)
{
    extern __shared__ __align__(16) char smem_raw[];
    SmK* sm = reinterpret_cast<SmK*>(smem_raw);

    const int ch   = blockIdx.x;
    const int b    = blockIdx.y;
    const int tid  = threadIdx.x;
    const int lane = tid & 31;
    const int warp = tid >> 5;

    const float4* Sg4 = reinterpret_cast<const float4*>(support + (size_t)b * NS * D);

    // load 28 x 256 chunk (rows 25..27 zero)
    for (int idx = tid; idx < SROWS * CW4; idx += 256) {
        int row = idx / CW4;
        int k4  = idx - row * CW4;
        float4 v = make_float4(0.f, 0.f, 0.f, 0.f);
        if (row < NS)
            v = Sg4[row * D4 + ch * CW4 + k4];
        float* dst = &sm->Sc[row * CP + k4 * 4];
        dst[0] = v.x; dst[1] = v.y; dst[2] = v.z; dst[3] = v.w;
    }
    __syncthreads();

    float* outp = kp + ((size_t)b * NCHUNK + ch) * NS * NS;

    // 28 upper-triangle 4x4 block tiles over 8 warps
    for (int t = warp; t < 28; t += 8) {
        const int bi = t_bi[t] * 4;
        const int bj = t_bj[t] * 4;

        float acc[16];                  // acc[r*4+s]
        #pragma unroll
        for (int m = 0; m < 16; m++) acc[m] = 0.f;

        #pragma unroll
        for (int it = 0; it < 2; it++) {
            const int k = (lane + 32 * it) * 4;
            float4 a[4];
            #pragma unroll
            for (int r = 0; r < 4; r++)
                a[r] = *reinterpret_cast<const float4*>(&sm->Sc[(bi + r) * CP + k]);
            #pragma unroll
            for (int s = 0; s < 4; s++) {
                float4 bv = *reinterpret_cast<const float4*>(&sm->Sc[(bj + s) * CP + k]);
                #pragma unroll
                for (int r = 0; r < 4; r++)
                    acc[r * 4 + s] += a[r].x * bv.x + a[r].y * bv.y +
                                      a[r].z * bv.z + a[r].w * bv.w;
            }
        }

        reduce16(acc, lane);

        if ((lane & 1) == 0) {
            const int m = (lane >> 1) & 15;
            const int i = bi + (m >> 2);
            const int j = bj + (m & 3);
            if (i < NS && j < NS) {
                // duplicate writes (diagonal tiles) are bit-identical
                outp[i * NS + j] = acc[0];
                outp[j * NS + i] = acc[0];
            }
        }
    }
}

// ---------------------------------------------------------------------------
// Kernel 2: fused: reduce K partials + block-parallel Gauss-Jordan + W = S^T A
//           grid(B), block 256   (R9 measured-good, FROZEN)
// ---------------------------------------------------------------------------
__global__ void __launch_bounds__(256, 5)
solve_w_kernel(const float* __restrict__ kp,
               const void* __restrict__ labels_raw,
               const float* __restrict__ support,
               float* __restrict__ wt_out)
{
    __shared__ float M[NS * AUGC];
    __shared__ float f[32];
    const int b    = blockIdx.x;
    const int tid  = threadIdx.x;
    const int lane = tid & 31;
    const int warp = tid >> 5;

    // ---- reduce 4 chunk partials + lambda*I (all threads) ----------------
    const float* p0 = kp + (size_t)b * NCHUNK * NS * NS;
    for (int s = tid; s < NS * NS; s += 256) {
        int i = s / NS, j = s - i * NS;
        float v = p0[s] + p0[s + NS * NS] + p0[s + 2 * NS * NS] + p0[s + 3 * NS * NS];
        if (i == j) v += 1.0f;
        M[i * AUGC + j] = v;
    }
    for (int s = tid; s < NS * (AUGC - NS); s += 256) {
        int i = s / (AUGC - NS), j = s - i * (AUGC - NS);
        M[i * AUGC + NS + j] = 0.0f;
    }
    __syncthreads();

    if (warp == 0) {
        // label dtype detection (int64 vs int32) via first 25 entries
        const int* li = reinterpret_cast<const int*>(labels_raw);
        int hi = (lane < NS) ? li[2 * lane + 1] : 0;
        unsigned nz = __ballot_sync(0xffffffffu, hi != 0);
        bool is64 = (nz == 0);

        if (lane < NS) {
            long long lbl;
            if (is64)
                lbl = reinterpret_cast<const long long*>(labels_raw)[(size_t)b * NS + lane];
            else
                lbl = (long long)li[(size_t)b * NS + lane];
            M[lane * AUGC + NS + (int)lbl] = 1.0f;
        }
    }
    __syncthreads();

    // ---- block-parallel Gauss-Jordan (SPD, no pivoting, column-skip) -----
    for (int p = 0; p < NS; p++) {
        const float inv = 1.0f / M[p * AUGC + p];
        if (tid < NS) {
            if (tid != p) f[tid] = M[tid * AUGC + p];
        } else if (tid >= 32 && tid < 64) {
            const int j = tid - 32;
            if (j >= p && j < 30) M[p * AUGC + j] *= inv;
        }
        __syncthreads();
        #pragma unroll
        for (int it = 0; it < 4; it++) {
            const int s = tid + it * 256;
            const int i = s >> 5;
            const int j = s & 31;
            if (i < NS && i != p && j >= p && j < 30)
                M[i * AUGC + j] -= f[i] * M[p * AUGC + j];
        }
        __syncthreads();
    }
    // A[i][c] at M[i][25 + c]

    // ---- W^T[c][k] = sum_i S[i][k] A[i][c]  (S from L2) -------------------
    const float4* Sg4 = reinterpret_cast<const float4*>(support + (size_t)b * NS * D);
    float4 acc[NWAY];
    #pragma unroll
    for (int c = 0; c < NWAY; c++) acc[c] = make_float4(0.f, 0.f, 0.f, 0.f);

    #pragma unroll
    for (int i = 0; i < NS; i++) {
        float4 s = __ldg(&Sg4[i * D4 + tid]);
        #pragma unroll
        for (int c = 0; c < NWAY; c++) {
            float a = M[i * AUGC + NS + c];
            acc[c].x += s.x * a; acc[c].y += s.y * a;
            acc[c].z += s.z * a; acc[c].w += s.w * a;
        }
    }
    float4* Wt4 = reinterpret_cast<float4*>(wt_out + (size_t)b * NWAY * D);
    #pragma unroll
    for (int c = 0; c < NWAY; c++)
        Wt4[c * D4 + tid] = acc[c];
}

// ---------------------------------------------------------------------------
// Kernel 3: logits = scale * Q @ W   (R4 measured-good config, FROZEN)
// ---------------------------------------------------------------------------
struct SmB { float Wt[NWAY * D]; };   // 20480 B

__global__ void __launch_bounds__(256, 5)
logits_kernel(const float* __restrict__ query,
              const float* __restrict__ wt_in,
              const float* __restrict__ scale,
              float* __restrict__ out,
              int NQ)
{
    extern __shared__ __align__(16) char smem_raw[];
    SmB* sm = reinterpret_cast<SmB*>(smem_raw);

    const int b    = blockIdx.y;
    const int sub  = blockIdx.x;
    const int tid  = threadIdx.x;
    const int lane = tid & 31;
    const int warp = tid >> 5;

    // load W^T tile (1280 float4 / 256 threads = 5 each)
    {
        const float4* src = reinterpret_cast<const float4*>(wt_in + (size_t)b * NWAY * D);
        float4* dst = reinterpret_cast<float4*>(sm->Wt);
        #pragma unroll
        for (int i = 0; i < 5; i++)
            dst[tid + i * 256] = src[tid + i * 256];
    }
    __syncthreads();

    const int row0 = sub * ROWS_PER_CTA;
    const int rows = min(ROWS_PER_CTA, NQ - row0);
    if (rows <= 0) return;

    const int r0 = warp * 2;
    const bool v0 = r0 < rows;
    const bool v1 = r0 + 1 < rows;
    if (!v0) return;

    const float* Qg = query + ((size_t)b * NQ + row0) * D;
    const float4* q0 = reinterpret_cast<const float4*>(Qg + (size_t)r0 * D);
    const float4* q1 = reinterpret_cast<const float4*>(Qg + (size_t)(r0 + 1) * D);

    float acc0[NWAY] = {0.f, 0.f, 0.f, 0.f, 0.f};
    float acc1[NWAY] = {0.f, 0.f, 0.f, 0.f, 0.f};

    #pragma unroll
    for (int it = 0; it < 8; it++) {
        const int k4 = lane + 32 * it;
        float4 qa = q0[k4];
        float4 qb = v1 ? q1[k4] : make_float4(0.f, 0.f, 0.f, 0.f);
        #pragma unroll
        for (int c = 0; c < NWAY; c++) {
            float4 w = *reinterpret_cast<const float4*>(&sm->Wt[c * D + k4 * 4]);
            acc0[c] += qa.x * w.x + qa.y * w.y + qa.z * w.z + qa.w * w.w;
            acc1[c] += qb.x * w.x + qb.y * w.y + qb.z * w.z + qb.w * w.w;
        }
    }

    const float scl = __ldg(scale);
    float* Ob = out + ((size_t)b * NQ + row0 + r0) * NWAY;
    #pragma unroll
    for (int c = 0; c < NWAY; c++) {
        float x = acc0[c], y = acc1[c];
        #pragma unroll
        for (int o = 16; o > 0; o >>= 1) {
            x += __shfl_xor_sync(0xffffffffu, x, o);
            y += __shfl_xor_sync(0xffffffffu, y, o);
        }
        if (lane == 0) {
            Ob[c] = scl * x;
            if (v1) Ob[NWAY + c] = scl * y;
        }
    }
}

extern "C" void kernel_launch(void* const* d_in, const int* in_sizes, int n_in,
                              void* d_out, int out_size)
{
    const float* query   = (const float*)d_in[0];
    const float* support = (const float*)d_in[1];
    const void*  labels  = d_in[2];
    const float* scale   = (const float*)d_in[3];

    const int B  = in_sizes[1] / (NS * D);
    const int NQ = in_sizes[0] / (B * D);

    float *kp, *wt;
    cudaGetSymbolAddress((void**)&kp, g_Kp);
    cudaGetSymbolAddress((void**)&wt, g_Wt);

    cudaFuncSetAttribute(kpart_kernel,
                         cudaFuncAttributeMaxDynamicSharedMemorySize, (int)sizeof(SmK));
    cudaFuncSetAttribute(logits_kernel,
                         cudaFuncAttributeMaxDynamicSharedMemorySize, (int)sizeof(SmB));

    dim3 g1(NCHUNK, B);
    kpart_kernel<<<g1, 256, sizeof(SmK)>>>(support, kp);

    solve_w_kernel<<<B, 256>>>(kp, labels, support, wt);

    dim3 g3((NQ + ROWS_PER_CTA - 1) / ROWS_PER_CTA, B);
    logits_kernel<<<g3, 256, sizeof(SmB)>>>(query, wt, scale, (float*)d_out, NQ);
}